// round 11
// baseline (speedup 1.0000x reference)
#include <cuda_runtime.h>
#include <cstdint>

// LSTM: B=2048, T=1024, I=8, H=64. out = sigmoid(h_T @ fc_w^T + fc_b), [B,1] fp32.
//
// R10: octet layout, 512-thread blocks, 2 blocks/SM -> 8 warps/SMSP (2x latency
// hiding). Thread = (unit u = tid>>3, lane-in-octet lo = (gsel, kq)): 2 outputs
// (i,f) or (g,o) of unit u, over K-quarter kq (16 h values + 2 x values).
// Per row: 5 LDS + 18 FFMA2; butterfly xor1+xor2 combines K-quarters (all kq
// lanes end with the full sum), bias added once per lane post-combine, xor4
// exchanges gate pairs -> owner lane (lo == row) holds all 4 gates. 18 u64
// weight regs/thread. ONE barrier/step, ping-pong h buffer. Grid 296.

#define TT   1024
#define RMAX 7

typedef unsigned long long u64;

__device__ __forceinline__ u64 pk2(float lo, float hi) {
    u64 r; asm("mov.b64 %0, {%1, %2};" : "=l"(r) : "f"(lo), "f"(hi)); return r;
}
__device__ __forceinline__ void upk2(u64 v, float& lo, float& hi) {
    asm("mov.b64 {%0, %1}, %2;" : "=f"(lo), "=f"(hi) : "l"(v));
}
__device__ __forceinline__ float tanhap(float x) {
    float r; asm("tanh.approx.f32 %0, %1;" : "=f"(r) : "f"(x)); return r;
}
__device__ __forceinline__ float sigap(float x) {
    return fmaf(0.5f, tanhap(0.5f * x), 0.5f);
}

// Row R: quarter-K dot on 2 outputs, butterfly-combine quarters, add bias,
// exchange gate pairs; owner lane (lo == R) stashes the 4 raw gate sums.
#define ROWG(R, RD) do {                                                            \
    u64 _a0 = 0ULL, _a1 = 0ULL, _h01, _h23, _hx;                                    \
    uint32_t _ad = (RD) + (R) * 288;                                                \
    _Pragma("unroll")                                                               \
    for (int q = 0; q < 4; ++q) {                                                   \
        asm("ld.shared.v2.u64 {%0, %1}, [%2];"                                      \
            : "=l"(_h01), "=l"(_h23) : "r"(_ad + kqoff + q * 16));                  \
        asm("fma.rn.f32x2 %0, %1, %2, %0;" : "+l"(_a0) : "l"(w0[2*q]),   "l"(_h01));\
        asm("fma.rn.f32x2 %0, %1, %2, %0;" : "+l"(_a1) : "l"(w1[2*q]),   "l"(_h01));\
        asm("fma.rn.f32x2 %0, %1, %2, %0;" : "+l"(_a0) : "l"(w0[2*q+1]), "l"(_h23));\
        asm("fma.rn.f32x2 %0, %1, %2, %0;" : "+l"(_a1) : "l"(w1[2*q+1]), "l"(_h23));\
    }                                                                               \
    asm("ld.shared.u64 %0, [%1];" : "=l"(_hx) : "r"(_ad + xoff));                   \
    asm("fma.rn.f32x2 %0, %1, %2, %0;" : "+l"(_a0) : "l"(wx0), "l"(_hx));           \
    asm("fma.rn.f32x2 %0, %1, %2, %0;" : "+l"(_a1) : "l"(wx1), "l"(_hx));           \
    float _e0, _o0, _e1, _o1;                                                       \
    upk2(_a0, _e0, _o0); upk2(_a1, _e1, _o1);                                       \
    float _s0 = _e0 + _o0, _s1 = _e1 + _o1;                                         \
    _s0 += __shfl_xor_sync(0xffffffffu, _s0, 1);                                    \
    _s1 += __shfl_xor_sync(0xffffffffu, _s1, 1);                                    \
    _s0 += __shfl_xor_sync(0xffffffffu, _s0, 2);                                    \
    _s1 += __shfl_xor_sync(0xffffffffu, _s1, 2);                                    \
    _s0 += biasA; _s1 += biasB;                                                     \
    float _r0 = __shfl_xor_sync(0xffffffffu, _s0, 4);                               \
    float _r1 = __shfl_xor_sync(0xffffffffu, _s1, 4);                               \
    if (lo == (R)) { st0 = _s0; st1 = _s1; st2 = _r0; st3 = _r1; }                  \
} while (0)

__global__ void __launch_bounds__(512, 2)
lstm_kernel(const float* __restrict__ x,     // [2048,1024,8]
            const float* __restrict__ Wih,   // [256,8]
            const float* __restrict__ Whh,   // [256,64]
            const float* __restrict__ bih,   // [256]
            const float* __restrict__ bhh,   // [256]
            const float* __restrict__ fcw,   // [64]
            const float* __restrict__ fcb,   // [1]
            float* __restrict__ out)         // [2048]
{
    __shared__ __align__(16) float s_h[2][RMAX][72];  // ping-pong: [buf][row][k]

    const int tid  = threadIdx.x;
    const int u    = tid >> 3;      // unit 0..63
    const int lo   = tid & 7;       // lane-in-octet
    const int kq   = lo & 3;        // K-quarter
    const int gsel = lo >> 2;       // 0: owns (i,f); 1: owns (g,o)
    const int bid  = blockIdx.x;
    const int nrows   = (bid < 272) ? 7 : 6;
    const int rowbase = (bid < 272) ? bid * 7 : 1904 + (bid - 272) * 6;
    const bool seven  = (nrows == 7);

    const int jA = gsel * 128 + u;        // i (or g)
    const int jB = gsel * 128 + 64 + u;   // f (or o)
    const uint32_t kqoff = (uint32_t)(kq * 64);        // h-quarter byte offset
    const uint32_t xoff  = (uint32_t)(256 + kq * 8);   // x-pair byte offset

    // ---- persistent weights: h-quarter (16) + x-pair (2) for outputs jA, jB ----
    u64 w0[8], w1[8];
#pragma unroll
    for (int q = 0; q < 8; ++q) {
        int k = kq * 16 + 2 * q;
        w0[q] = pk2(Whh[jA * 64 + k], Whh[jA * 64 + k + 1]);
        w1[q] = pk2(Whh[jB * 64 + k], Whh[jB * 64 + k + 1]);
    }
    const u64 wx0 = pk2(Wih[jA * 8 + 2 * kq], Wih[jA * 8 + 2 * kq + 1]);
    const u64 wx1 = pk2(Wih[jB * 8 + 2 * kq], Wih[jB * 8 + 2 * kq + 1]);
    // Added once per lane AFTER xor1+xor2 (full sum present on every kq lane);
    // xor4 only exchanges between gate-pair groups, no re-summation -> full bias.
    const float biasA = bih[jA] + bhh[jA];
    const float biasB = bih[jB] + bhh[jB];

    // ---- owned state: lane lo updates (row lo, unit u) ----
    const bool hasRow = (lo < nrows);
    float c = 0.0f;
    float st0 = 0, st1 = 0, st2 = 0, st3 = 0;

    // ---- x stagers: threads 0..55 -> (row sr = tid>>3, input sxi = tid&7) ----
    const int  sr  = tid >> 3;
    const int  sxi = tid & 7;
    const bool isStager = (tid < 56) && (sr < nrows);
    const float* xrow = x + (size_t)(rowbase + sr) * (TT * 8) + sxi;

    const uint32_t hB0 = (uint32_t)__cvta_generic_to_shared(&s_h[0][0][0]);
    const uint32_t hB1 = (uint32_t)__cvta_generic_to_shared(&s_h[1][0][0]);

    // ---- init buf0: h = 0, x(0) staged ----
    for (int i = tid; i < RMAX * 72; i += 512)
        (&s_h[0][0][0])[i] = 0.0f;
    __syncthreads();
    if (isStager) s_h[0][sr][64 + sxi] = __ldg(xrow);
    __syncthreads();

    uint32_t rd = hB0, wr = hB1;

#pragma unroll 1
    for (int t = 0; t < TT; ++t) {
        float xn = 0.0f;
        const bool pre = isStager && (t + 1 < TT);
        if (pre) xn = __ldg(xrow + (t + 1) * 8);

        ROWG(0, rd); ROWG(1, rd); ROWG(2, rd); ROWG(3, rd);
        ROWG(4, rd); ROWG(5, rd);
        if (seven) ROWG(6, rd);

        // ---- owner update: all 4 gates in stash regs ----
        if (hasRow) {
            float gi = gsel ? st2 : st0;
            float gf = gsel ? st3 : st1;
            float gg = gsel ? st0 : st2;
            float go = gsel ? st1 : st3;
            c = fmaf(sigap(gf), c, sigap(gi) * tanhap(gg));
            float hv = sigap(go) * tanhap(c);
            asm volatile("st.shared.f32 [%0], %1;"
                         :: "r"(wr + lo * 288 + u * 4), "f"(hv) : "memory");
        }
        if (pre) {
            asm volatile("st.shared.f32 [%0], %1;"
                         :: "r"(wr + sr * 288 + (64 + sxi) * 4), "f"(xn) : "memory");
        }
        __syncthreads();

        uint32_t tmp = rd; rd = wr; wr = tmp;
    }

    // TT even -> final h lives in buf0
    if (tid < nrows) {
        const float* hp = s_h[0][tid];
        float acc = fcb[0];
#pragma unroll
        for (int uu = 0; uu < 64; ++uu)
            acc = fmaf(hp[uu], fcw[uu], acc);
        out[rowbase + tid] = sigap(acc);
    }
}

extern "C" void kernel_launch(void* const* d_in, const int* in_sizes, int n_in,
                              void* d_out, int out_size)
{
    const float* x   = (const float*)d_in[0];
    const float* Wih = (const float*)d_in[1];
    const float* Whh = (const float*)d_in[2];
    const float* bih = (const float*)d_in[3];
    const float* bhh = (const float*)d_in[4];
    const float* fcw = (const float*)d_in[5];
    const float* fcb = (const float*)d_in[6];
    lstm_kernel<<<296, 512>>>(x, Wih, Whh, bih, bhh, fcw, fcb, (float*)d_out);
}

// round 12
// speedup vs baseline: 1.6454x; 1.6454x over previous
#include <cuda_runtime.h>
#include <cstdint>

// LSTM: B=2048, T=1024, I=8, H=64. out = sigmoid(h_T @ fc_w^T + fc_b), [B,1] fp32.
//
// R11 = R10 (octet layout, 512-thread blocks, 2 blocks/SM, 8 warps/SMSP) with:
//  (a) bank-conflict-free rotated read pattern: lane kq reads chunk q at
//      kq*64 + ((q+kq)&3)*16  -> 4 distinct addresses land in 16 disjoint banks
//      (weights permuted at init to match; h storage stays natural),
//  (b) deferred gate-pair exchange: per-row stash of own-pair sums (bias folded
//      in), ONE xor4 shfl pair at step end instead of two per row
//      (shfl/thread/step 42 -> 30).
// Per row: 5 LDS + 18 FFMA2 + xor1 + xor2. ONE barrier/step, ping-pong h.

#define TT   1024
#define RMAX 7

typedef unsigned long long u64;

__device__ __forceinline__ u64 pk2(float lo, float hi) {
    u64 r; asm("mov.b64 %0, {%1, %2};" : "=l"(r) : "f"(lo), "f"(hi)); return r;
}
__device__ __forceinline__ void upk2(u64 v, float& lo, float& hi) {
    asm("mov.b64 {%0, %1}, %2;" : "=f"(lo), "=f"(hi) : "l"(v));
}
__device__ __forceinline__ float tanhap(float x) {
    float r; asm("tanh.approx.f32 %0, %1;" : "=f"(r) : "f"(x)); return r;
}
__device__ __forceinline__ float sigap(float x) {
    return fmaf(0.5f, tanhap(0.5f * x), 0.5f);
}

// Row R: quarter-K dot (rotated, conflict-free), fold, xor1+xor2 combine
// (all kq lanes end with the full own-pair sums); stash w/ bias if owner row.
#define ROWG(R, RD) do {                                                            \
    u64 _a0 = 0ULL, _a1 = 0ULL, _h01, _h23, _hx;                                    \
    uint32_t _rb = (RD) + (R) * 288;                                                \
    asm("ld.shared.v2.u64 {%0, %1}, [%2];" : "=l"(_h01), "=l"(_h23) : "r"(_rb+ro0));\
    asm("fma.rn.f32x2 %0, %1, %2, %0;" : "+l"(_a0) : "l"(w0[0]), "l"(_h01));        \
    asm("fma.rn.f32x2 %0, %1, %2, %0;" : "+l"(_a1) : "l"(w1[0]), "l"(_h01));        \
    asm("fma.rn.f32x2 %0, %1, %2, %0;" : "+l"(_a0) : "l"(w0[1]), "l"(_h23));        \
    asm("fma.rn.f32x2 %0, %1, %2, %0;" : "+l"(_a1) : "l"(w1[1]), "l"(_h23));        \
    asm("ld.shared.v2.u64 {%0, %1}, [%2];" : "=l"(_h01), "=l"(_h23) : "r"(_rb+ro1));\
    asm("fma.rn.f32x2 %0, %1, %2, %0;" : "+l"(_a0) : "l"(w0[2]), "l"(_h01));        \
    asm("fma.rn.f32x2 %0, %1, %2, %0;" : "+l"(_a1) : "l"(w1[2]), "l"(_h01));        \
    asm("fma.rn.f32x2 %0, %1, %2, %0;" : "+l"(_a0) : "l"(w0[3]), "l"(_h23));        \
    asm("fma.rn.f32x2 %0, %1, %2, %0;" : "+l"(_a1) : "l"(w1[3]), "l"(_h23));        \
    asm("ld.shared.v2.u64 {%0, %1}, [%2];" : "=l"(_h01), "=l"(_h23) : "r"(_rb+ro2));\
    asm("fma.rn.f32x2 %0, %1, %2, %0;" : "+l"(_a0) : "l"(w0[4]), "l"(_h01));        \
    asm("fma.rn.f32x2 %0, %1, %2, %0;" : "+l"(_a1) : "l"(w1[4]), "l"(_h01));        \
    asm("fma.rn.f32x2 %0, %1, %2, %0;" : "+l"(_a0) : "l"(w0[5]), "l"(_h23));        \
    asm("fma.rn.f32x2 %0, %1, %2, %0;" : "+l"(_a1) : "l"(w1[5]), "l"(_h23));        \
    asm("ld.shared.v2.u64 {%0, %1}, [%2];" : "=l"(_h01), "=l"(_h23) : "r"(_rb+ro3));\
    asm("fma.rn.f32x2 %0, %1, %2, %0;" : "+l"(_a0) : "l"(w0[6]), "l"(_h01));        \
    asm("fma.rn.f32x2 %0, %1, %2, %0;" : "+l"(_a1) : "l"(w1[6]), "l"(_h01));        \
    asm("fma.rn.f32x2 %0, %1, %2, %0;" : "+l"(_a0) : "l"(w0[7]), "l"(_h23));        \
    asm("fma.rn.f32x2 %0, %1, %2, %0;" : "+l"(_a1) : "l"(w1[7]), "l"(_h23));        \
    asm("ld.shared.u64 %0, [%1];" : "=l"(_hx) : "r"(_rb + xoff));                   \
    asm("fma.rn.f32x2 %0, %1, %2, %0;" : "+l"(_a0) : "l"(wx0), "l"(_hx));           \
    asm("fma.rn.f32x2 %0, %1, %2, %0;" : "+l"(_a1) : "l"(wx1), "l"(_hx));           \
    float _e0, _o0, _e1, _o1;                                                       \
    upk2(_a0, _e0, _o0); upk2(_a1, _e1, _o1);                                       \
    float _s0 = _e0 + _o0, _s1 = _e1 + _o1;                                         \
    _s0 += __shfl_xor_sync(0xffffffffu, _s0, 1);                                    \
    _s1 += __shfl_xor_sync(0xffffffffu, _s1, 1);                                    \
    _s0 += __shfl_xor_sync(0xffffffffu, _s0, 2);                                    \
    _s1 += __shfl_xor_sync(0xffffffffu, _s1, 2);                                    \
    if ((R) < 4) { if (kq == (R))     { sA0 = _s0 + biasA; sA1 = _s1 + biasB; } }   \
    else         { if (kq == (R) - 4) { sB0 = _s0 + biasA; sB1 = _s1 + biasB; } }   \
} while (0)

__global__ void __launch_bounds__(512, 2)
lstm_kernel(const float* __restrict__ x,     // [2048,1024,8]
            const float* __restrict__ Wih,   // [256,8]
            const float* __restrict__ Whh,   // [256,64]
            const float* __restrict__ bih,   // [256]
            const float* __restrict__ bhh,   // [256]
            const float* __restrict__ fcw,   // [64]
            const float* __restrict__ fcb,   // [1]
            float* __restrict__ out)         // [2048]
{
    __shared__ __align__(16) float s_h[2][RMAX][72];  // ping-pong: [buf][row][k]

    const int tid  = threadIdx.x;
    const int u    = tid >> 3;      // unit 0..63
    const int lo   = tid & 7;       // lane-in-octet
    const int kq   = lo & 3;        // K-quarter
    const int gsel = lo >> 2;       // 0: owns (i,f); 1: owns (g,o)
    const int bid  = blockIdx.x;
    const int nrows   = (bid < 272) ? 7 : 6;
    const int rowbase = (bid < 272) ? bid * 7 : 1904 + (bid - 272) * 6;
    const bool seven  = (nrows == 7);

    const int jA = gsel * 128 + u;        // i (or g)
    const int jB = gsel * 128 + 64 + u;   // f (or o)

    // Rotated, conflict-free chunk addresses (bytes): kq*64 + ((q+kq)&3)*16
    const uint32_t ro0 = (uint32_t)(kq * 64 + ((0 + kq) & 3) * 16);
    const uint32_t ro1 = (uint32_t)(kq * 64 + ((1 + kq) & 3) * 16);
    const uint32_t ro2 = (uint32_t)(kq * 64 + ((2 + kq) & 3) * 16);
    const uint32_t ro3 = (uint32_t)(kq * 64 + ((3 + kq) & 3) * 16);
    const uint32_t xoff = (uint32_t)(256 + kq * 8);    // x-pair (disjoint banks)

    // ---- persistent weights, permuted to match the rotated read order ----
    u64 w0[8], w1[8];
#pragma unroll
    for (int q = 0; q < 4; ++q) {
        int k = kq * 16 + ((q + kq) & 3) * 4;          // 4 floats at this chunk
        w0[2 * q]     = pk2(Whh[jA * 64 + k],     Whh[jA * 64 + k + 1]);
        w0[2 * q + 1] = pk2(Whh[jA * 64 + k + 2], Whh[jA * 64 + k + 3]);
        w1[2 * q]     = pk2(Whh[jB * 64 + k],     Whh[jB * 64 + k + 1]);
        w1[2 * q + 1] = pk2(Whh[jB * 64 + k + 2], Whh[jB * 64 + k + 3]);
    }
    const u64 wx0 = pk2(Wih[jA * 8 + 2 * kq], Wih[jA * 8 + 2 * kq + 1]);
    const u64 wx1 = pk2(Wih[jB * 8 + 2 * kq], Wih[jB * 8 + 2 * kq + 1]);
    const float biasA = bih[jA] + bhh[jA];   // folded in at stash (once per value)
    const float biasB = bih[jB] + bhh[jB];

    // ---- owned state: gsel0 lane updates row kq; gsel1 lane updates row 4+kq ----
    const int  myrow  = gsel ? (4 + kq) : kq;
    const bool hasRow = (myrow < nrows);
    float c = 0.0f;
    float sA0 = 0, sA1 = 0, sB0 = 0, sB1 = 0;   // own-pair sums, rows kq / 4+kq

    // ---- x stagers: threads 0..55 -> (row sr, input sxi) ----
    const int  sr  = tid >> 3;
    const int  sxi = tid & 7;
    const bool isStager = (tid < 56) && (sr < nrows);
    const float* xrow = x + (size_t)(rowbase + sr) * (TT * 8) + sxi;

    const uint32_t hB0 = (uint32_t)__cvta_generic_to_shared(&s_h[0][0][0]);
    const uint32_t hB1 = (uint32_t)__cvta_generic_to_shared(&s_h[1][0][0]);

    // ---- init buf0: h = 0, x(0) staged ----
    for (int i = tid; i < RMAX * 72; i += 512)
        (&s_h[0][0][0])[i] = 0.0f;
    __syncthreads();
    if (isStager) s_h[0][sr][64 + sxi] = __ldg(xrow);
    __syncthreads();

    uint32_t rd = hB0, wr = hB1;

#pragma unroll 1
    for (int t = 0; t < TT; ++t) {
        float xn = 0.0f;
        const bool pre = isStager && (t + 1 < TT);
        if (pre) xn = __ldg(xrow + (t + 1) * 8);

        ROWG(0, rd); ROWG(1, rd); ROWG(2, rd); ROWG(3, rd);
        ROWG(4, rd); ROWG(5, rd);
        if (seven) ROWG(6, rd);

        // ---- deferred gate-pair exchange: ONE xor4 pair for the whole step ----
        {
            // send what the partner (gsel flipped, same kq, same u) needs
            float send0 = gsel ? sA0 : sB0;
            float send1 = gsel ? sA1 : sB1;
            float recv0 = __shfl_xor_sync(0xffffffffu, send0, 4);
            float recv1 = __shfl_xor_sync(0xffffffffu, send1, 4);
            if (hasRow) {
                // gsel0 (row kq):   own (i,f) = sA0,sA1; partner (g,o) = recv
                // gsel1 (row 4+kq): own (g,o) = sB0,sB1; partner (i,f) = recv
                float gi = gsel ? recv0 : sA0;
                float gf = gsel ? recv1 : sA1;
                float gg = gsel ? sB0   : recv0;
                float go = gsel ? sB1   : recv1;
                c = fmaf(sigap(gf), c, sigap(gi) * tanhap(gg));
                float hv = sigap(go) * tanhap(c);
                asm volatile("st.shared.f32 [%0], %1;"
                             :: "r"(wr + myrow * 288 + u * 4), "f"(hv) : "memory");
            }
        }
        if (pre) {
            asm volatile("st.shared.f32 [%0], %1;"
                         :: "r"(wr + sr * 288 + (64 + sxi) * 4), "f"(xn) : "memory");
        }
        __syncthreads();

        uint32_t tmp = rd; rd = wr; wr = tmp;
    }

    // TT even -> final h lives in buf0
    if (tid < nrows) {
        const float* hp = s_h[0][tid];
        float acc = fcb[0];
#pragma unroll
        for (int uu = 0; uu < 64; ++uu)
            acc = fmaf(hp[uu], fcw[uu], acc);
        out[rowbase + tid] = sigap(acc);
    }
}

extern "C" void kernel_launch(void* const* d_in, const int* in_sizes, int n_in,
                              void* d_out, int out_size)
{
    const float* x   = (const float*)d_in[0];
    const float* Wih = (const float*)d_in[1];
    const float* Whh = (const float*)d_in[2];
    const float* bih = (const float*)d_in[3];
    const float* bhh = (const float*)d_in[4];
    const float* fcw = (const float*)d_in[5];
    const float* fcb = (const float*)d_in[6];
    lstm_kernel<<<296, 512>>>(x, Wih, Whh, bih, bhh, fcw, fcb, (float*)d_out);
}

// round 14
// speedup vs baseline: 2.0397x; 1.2396x over previous
#include <cuda_runtime.h>
#include <cstdint>

// LSTM: B=2048, T=1024, I=8, H=64. out = sigmoid(h_T @ fc_w^T + fc_b), [B,1] fp32.
//
// R13 = R12 (4 gate-outputs per thread over K/4 -> halved smem bytes) with the
// kq-reduction done by a 2-stage shfl butterfly (xor 8, xor 16) instead of the
// unsupported redux.sync.add.f32. L1 model: LDS.128 = 4 wavefronts always, so
// smem reads are pure bandwidth; sharing each h-read across 4 outputs puts the
// L1 cost (~1008 cyc/SM-step) under the FFMA2 floor (2016 cyc) -> FMA-bound.
// 256 threads, 2 blocks/SM, ONE barrier/step, ping-pong h buffer. Grid 296.

#define TT   1024
#define RMAX 7

typedef unsigned long long u64;

__device__ __forceinline__ u64 pk2(float lo, float hi) {
    u64 r; asm("mov.b64 %0, {%1, %2};" : "=l"(r) : "f"(lo), "f"(hi)); return r;
}
__device__ __forceinline__ void upk2(u64 v, float& lo, float& hi) {
    asm("mov.b64 {%0, %1}, %2;" : "=f"(lo), "=f"(hi) : "l"(v));
}
__device__ __forceinline__ float tanhap(float x) {
    float r; asm("tanh.approx.f32 %0, %1;" : "=f"(r) : "f"(x)); return r;
}
__device__ __forceinline__ float sigap(float x) {
    return fmaf(0.5f, tanhap(0.5f * x), 0.5f);
}

// Row R: 18-K dot on the 4 gates of unit u, fold, butterfly-reduce over the
// kq group (lanes {l, l+8, l+16, l+24}); owner lane updates c/h immediately.
#define ROWG(R, RD, WR) do {                                                        \
    u64 _a0 = 0ULL, _a1 = 0ULL, _a2 = 0ULL, _a3 = 0ULL, _h01, _h23, _hx;            \
    uint32_t _ad = (RD) + (R) * 320 + kqoff;                                        \
    _Pragma("unroll")                                                               \
    for (int q = 0; q < 4; ++q) {                                                   \
        asm("ld.shared.v2.u64 {%0, %1}, [%2];"                                      \
            : "=l"(_h01), "=l"(_h23) : "r"(_ad + q * 16));                          \
        asm("fma.rn.f32x2 %0, %1, %2, %0;" : "+l"(_a0) : "l"(w0[2*q]),   "l"(_h01));\
        asm("fma.rn.f32x2 %0, %1, %2, %0;" : "+l"(_a1) : "l"(w1[2*q]),   "l"(_h01));\
        asm("fma.rn.f32x2 %0, %1, %2, %0;" : "+l"(_a2) : "l"(w2[2*q]),   "l"(_h01));\
        asm("fma.rn.f32x2 %0, %1, %2, %0;" : "+l"(_a3) : "l"(w3[2*q]),   "l"(_h01));\
        asm("fma.rn.f32x2 %0, %1, %2, %0;" : "+l"(_a0) : "l"(w0[2*q+1]), "l"(_h23));\
        asm("fma.rn.f32x2 %0, %1, %2, %0;" : "+l"(_a1) : "l"(w1[2*q+1]), "l"(_h23));\
        asm("fma.rn.f32x2 %0, %1, %2, %0;" : "+l"(_a2) : "l"(w2[2*q+1]), "l"(_h23));\
        asm("fma.rn.f32x2 %0, %1, %2, %0;" : "+l"(_a3) : "l"(w3[2*q+1]), "l"(_h23));\
    }                                                                               \
    asm("ld.shared.u64 %0, [%1];" : "=l"(_hx) : "r"(_ad + 64));                     \
    asm("fma.rn.f32x2 %0, %1, %2, %0;" : "+l"(_a0) : "l"(w0[8]), "l"(_hx));         \
    asm("fma.rn.f32x2 %0, %1, %2, %0;" : "+l"(_a1) : "l"(w1[8]), "l"(_hx));         \
    asm("fma.rn.f32x2 %0, %1, %2, %0;" : "+l"(_a2) : "l"(w2[8]), "l"(_hx));         \
    asm("fma.rn.f32x2 %0, %1, %2, %0;" : "+l"(_a3) : "l"(w3[8]), "l"(_hx));         \
    float _e, _o, _f0, _f1, _f2, _f3;                                               \
    upk2(_a0, _e, _o); _f0 = _e + _o;                                               \
    upk2(_a1, _e, _o); _f1 = _e + _o;                                               \
    upk2(_a2, _e, _o); _f2 = _e + _o;                                               \
    upk2(_a3, _e, _o); _f3 = _e + _o;                                               \
    _f0 += __shfl_xor_sync(0xffffffffu, _f0, 8);                                    \
    _f1 += __shfl_xor_sync(0xffffffffu, _f1, 8);                                    \
    _f2 += __shfl_xor_sync(0xffffffffu, _f2, 8);                                    \
    _f3 += __shfl_xor_sync(0xffffffffu, _f3, 8);                                    \
    _f0 += __shfl_xor_sync(0xffffffffu, _f0, 16);                                   \
    _f1 += __shfl_xor_sync(0xffffffffu, _f1, 16);                                   \
    _f2 += __shfl_xor_sync(0xffffffffu, _f2, 16);                                   \
    _f3 += __shfl_xor_sync(0xffffffffu, _f3, 16);                                   \
    const bool _own = ((R) < 4) ? (kq == (R)) : (kq == (R) - 4);                    \
    if (_own) {                                                                     \
        float _gi = sigap(_f0 + bI);                                                \
        float _gf = sigap(_f1 + bF);                                                \
        float _gg = tanhap(_f2 + bG);                                               \
        float _go = sigap(_f3 + bO);                                                \
        if ((R) < 4) {                                                              \
            cLo = fmaf(_gf, cLo, _gi * _gg);                                        \
            float _hv = _go * tanhap(cLo);                                          \
            asm volatile("st.shared.f32 [%0], %1;"                                  \
                         :: "r"((WR) + (R) * 320 + ust), "f"(_hv) : "memory");      \
        } else {                                                                    \
            cHi = fmaf(_gf, cHi, _gi * _gg);                                        \
            float _hv = _go * tanhap(cHi);                                          \
            asm volatile("st.shared.f32 [%0], %1;"                                  \
                         :: "r"((WR) + (R) * 320 + ust), "f"(_hv) : "memory");      \
        }                                                                           \
    }                                                                               \
} while (0)

__global__ void __launch_bounds__(256, 2)
lstm_kernel(const float* __restrict__ x,     // [2048,1024,8]
            const float* __restrict__ Wih,   // [256,8]
            const float* __restrict__ Whh,   // [256,64]
            const float* __restrict__ bih,   // [256]
            const float* __restrict__ bhh,   // [256]
            const float* __restrict__ fcw,   // [64]
            const float* __restrict__ fcb,   // [1]
            float* __restrict__ out)         // [2048]
{
    // [buf][row][4 segs x 20 floats]; logical k -> idx = (k/18)*20 + (k%18)
    __shared__ __align__(16) float s_h[2][RMAX][80];

    const int tid  = threadIdx.x;
    const int lane = tid & 31;
    const int wid  = tid >> 5;
    const int ulow = lane & 7;          // unit-low: kq group = {l, l+8, l+16, l+24}
    const int kq   = (lane >> 3) & 3;   // K-quarter: k in [18kq, 18kq+18)
    const int u    = wid * 8 + ulow;    // unit 0..63
    const int bid  = blockIdx.x;
    const int nrows   = (bid < 272) ? 7 : 6;
    const int rowbase = (bid < 272) ? bid * 7 : 1904 + (bid - 272) * 6;
    const bool seven  = (nrows == 7);

    const uint32_t kqoff = (uint32_t)(kq * 80);                 // segment base (bytes)
    const uint32_t ust   = (uint32_t)(((u / 18) * 20 + (u % 18)) * 4);  // h store off

    // ---- persistent weights: K-chunk [18kq,18kq+18) of outputs u,64+u,128+u,192+u ----
    u64 w0[9], w1[9], w2[9], w3[9];
#pragma unroll
    for (int q = 0; q < 9; ++q) {
        int k = kq * 18 + 2 * q;
#define WLD(J) pk2((k < 64) ? Whh[(J) * 64 + k]     : Wih[(J) * 8 + (k - 64)],      \
                   (k + 1 < 64) ? Whh[(J) * 64 + k + 1] : Wih[(J) * 8 + (k + 1 - 64)])
        w0[q] = WLD(u);
        w1[q] = WLD(64 + u);
        w2[q] = WLD(128 + u);
        w3[q] = WLD(192 + u);
#undef WLD
    }
    const float bI = bih[u] + bhh[u];
    const float bF = bih[64 + u] + bhh[64 + u];
    const float bG = bih[128 + u] + bhh[128 + u];
    const float bO = bih[192 + u] + bhh[192 + u];

    // ---- owner state: lane kq owns rows kq and kq+4 ----
    float cLo = 0.0f, cHi = 0.0f;

    // ---- x stagers: threads 0..55 -> (row sr, input sxi); x_i -> idx 70+i ----
    const int  sr  = tid >> 3;
    const int  sxi = tid & 7;
    const bool isStager = (tid < 56) && (sr < nrows);
    const float* xrow = x + (size_t)(rowbase + sr) * (TT * 8) + sxi;

    const uint32_t hB0 = (uint32_t)__cvta_generic_to_shared(&s_h[0][0][0]);
    const uint32_t hB1 = (uint32_t)__cvta_generic_to_shared(&s_h[1][0][0]);

    // ---- init buf0: zero (incl pads), stage x(0) ----
    for (int i = tid; i < 2 * RMAX * 80; i += 256)
        (&s_h[0][0][0])[i] = 0.0f;
    __syncthreads();
    if (isStager) s_h[0][sr][70 + sxi] = __ldg(xrow);
    __syncthreads();

    uint32_t rd = hB0, wr = hB1;

#pragma unroll 1
    for (int t = 0; t < TT; ++t) {
        float xn = 0.0f;
        const bool pre = isStager && (t + 1 < TT);
        if (pre) xn = __ldg(xrow + (t + 1) * 8);

        ROWG(0, rd, wr); ROWG(1, rd, wr); ROWG(2, rd, wr); ROWG(3, rd, wr);
        if (pre) {
            asm volatile("st.shared.f32 [%0], %1;"
                         :: "r"(wr + sr * 320 + (70 + sxi) * 4), "f"(xn) : "memory");
        }
        ROWG(4, rd, wr); ROWG(5, rd, wr);
        if (seven) ROWG(6, rd, wr);

        __syncthreads();
        uint32_t tmp = rd; rd = wr; wr = tmp;
    }

    // TT even -> final h lives in buf0 (padded layout)
    if (tid < nrows) {
        const float* hp = s_h[0][tid];
        float acc = fcb[0];
#pragma unroll
        for (int k = 0; k < 64; ++k)
            acc = fmaf(hp[(k / 18) * 20 + (k % 18)], fcw[k], acc);
        out[rowbase + tid] = sigap(acc);
    }
}

extern "C" void kernel_launch(void* const* d_in, const int* in_sizes, int n_in,
                              void* d_out, int out_size)
{
    const float* x   = (const float*)d_in[0];
    const float* Wih = (const float*)d_in[1];
    const float* Whh = (const float*)d_in[2];
    const float* bih = (const float*)d_in[3];
    const float* bhh = (const float*)d_in[4];
    const float* fcw = (const float*)d_in[5];
    const float* fcb = (const float*)d_in[6];
    lstm_kernel<<<296, 256>>>(x, Wih, Whh, bih, bhh, fcw, fcb, (float*)d_out);
}

// round 15
// speedup vs baseline: 2.4322x; 1.1925x over previous
#include <cuda_runtime.h>
#include <cstdint>

// LSTM: B=2048, T=1024, I=8, H=64. out = sigmoid(h_T @ fc_w^T + fc_b), [B,1] fp32.
//
// R14 = R9-1925 (quad-gate: u=tid>>2, lane-in-quad = (K-half, gate-pair); 2
// outputs x 36 K in 36 packed f32x2 regs; 9 LDS + 36 FFMA2 + 4 shfl per row;
// split owner updates; ONE barrier/step; ping-pong h) + 2-row SOFTWARE
// PIPELINING: two acc sets alive, RED(r) issued after DOT(r+1) so each row's
// fold/shfl chain hides under the next row's FMA stream. Phantom row 6 always
// computed (zero-initialized, self-contained) to kill the nrows branch.
// Grid 296 = 2 blocks on every SM, 256 threads.

#define TT   1024
#define RMAX 7

typedef unsigned long long u64;

__device__ __forceinline__ u64 pk2(float lo, float hi) {
    u64 r; asm("mov.b64 %0, {%1, %2};" : "=l"(r) : "f"(lo), "f"(hi)); return r;
}
__device__ __forceinline__ void upk2(u64 v, float& lo, float& hi) {
    asm("mov.b64 {%0, %1}, %2;" : "=f"(lo), "=f"(hi) : "l"(v));
}
__device__ __forceinline__ float tanhap(float x) {
    float r; asm("tanh.approx.f32 %0, %1;" : "=f"(r) : "f"(x)); return r;
}
__device__ __forceinline__ float sigap(float x) {
    return fmaf(0.5f, tanhap(0.5f * x), 0.5f);
}

// Half-K dot of row R into accumulators A0 (output jA), A1 (output jB).
#define DOT(R, A0, A1) do {                                                         \
    uint32_t _ad = rd + (R) * 288 + khoff;                                          \
    u64 _h01, _h23;                                                                 \
    A0 = bias0; A1 = bias1;                                                         \
    _Pragma("unroll")                                                               \
    for (int q = 0; q < 9; ++q) {                                                   \
        asm("ld.shared.v2.u64 {%0, %1}, [%2];"                                      \
            : "=l"(_h01), "=l"(_h23) : "r"(_ad + q * 16));                          \
        asm("fma.rn.f32x2 %0, %1, %2, %0;" : "+l"(A0) : "l"(w0[2*q]),   "l"(_h01)); \
        asm("fma.rn.f32x2 %0, %1, %2, %0;" : "+l"(A1) : "l"(w1[2*q]),   "l"(_h01)); \
        asm("fma.rn.f32x2 %0, %1, %2, %0;" : "+l"(A0) : "l"(w0[2*q+1]), "l"(_h23)); \
        asm("fma.rn.f32x2 %0, %1, %2, %0;" : "+l"(A1) : "l"(w1[2*q+1]), "l"(_h23)); \
    }                                                                               \
} while (0)

// Fold + quad all-gather for row R; owner lane stashes the 4 raw values.
#define RED(R, A0, A1) do {                                                         \
    float _e0, _o0, _e1, _o1;                                                       \
    upk2(A0, _e0, _o0); upk2(A1, _e1, _o1);                                         \
    float _s0 = _e0 + _o0, _s1 = _e1 + _o1;                                         \
    _s0 += __shfl_xor_sync(0xffffffffu, _s0, 1);   /* combine K-halves */           \
    _s1 += __shfl_xor_sync(0xffffffffu, _s1, 1);                                    \
    float _r0 = __shfl_xor_sync(0xffffffffu, _s0, 2);  /* partner gate pair */      \
    float _r1 = __shfl_xor_sync(0xffffffffu, _s1, 2);                               \
    if ((R) < 4) { if (lq == (R))     { sA0=_s0; sA1=_s1; rA0=_r0; rA1=_r1; } }     \
    else         { if (lq == (R) - 4) { sB0=_s0; sB1=_s1; rB0=_r0; rB1=_r1; } }     \
} while (0)

__global__ void __launch_bounds__(256, 2)
lstm_kernel(const float* __restrict__ x,     // [2048,1024,8]
            const float* __restrict__ Wih,   // [256,8]
            const float* __restrict__ Whh,   // [256,64]
            const float* __restrict__ bih,   // [256]
            const float* __restrict__ bhh,   // [256]
            const float* __restrict__ fcw,   // [64]
            const float* __restrict__ fcb,   // [1]
            float* __restrict__ out)         // [2048]
{
    __shared__ __align__(16) float s_h[2][RMAX][72];  // ping-pong: [buf][row][k]

    const int tid  = threadIdx.x;
    const int u    = tid >> 2;      // unit 0..63
    const int lq   = tid & 3;       // lane-in-quad
    const int kh   = lq & 1;        // K-half
    const int gsel = lq >> 1;       // 0: owns (i,f); 1: owns (g,o)
    const int bid  = blockIdx.x;
    const int nrows   = (bid < 272) ? 7 : 6;
    const int rowbase = (bid < 272) ? bid * 7 : 1904 + (bid - 272) * 6;

    const int jA = gsel * 128 + u;        // i (or g)
    const int jB = gsel * 128 + 64 + u;   // f (or o)
    const int kb = kh * 36;
    const uint32_t khoff = (uint32_t)(kb * 4);

    // ---- persistent weights: this K-half of outputs jA, jB ----
    u64 w0[18], w1[18];
#pragma unroll
    for (int q = 0; q < 18; ++q) {
        int k = kb + 2 * q;
        float a = (k     < 64) ? Whh[jA * 64 + k]     : Wih[jA * 8 + (k - 64)];
        float b = (k + 1 < 64) ? Whh[jA * 64 + k + 1] : Wih[jA * 8 + (k + 1 - 64)];
        float c = (k     < 64) ? Whh[jB * 64 + k]     : Wih[jB * 8 + (k - 64)];
        float d = (k + 1 < 64) ? Whh[jB * 64 + k + 1] : Wih[jB * 8 + (k + 1 - 64)];
        w0[q] = pk2(a, b);
        w1[q] = pk2(c, d);
    }
    u64 bias0 = 0ULL, bias1 = 0ULL;
    if (kh == 0) {   // bias counted exactly once per output
        bias0 = pk2(bih[jA] + bhh[jA], 0.0f);
        bias1 = pk2(bih[jB] + bhh[jB], 0.0f);
    }

    // ---- owned rows: rowA = lq (0..3), rowB = lq+4 (lq<3 only; row 7 absent) ----
    const int rowA = lq, rowB = lq + 4;
    const bool hasB = (lq < 3);
    float cA = 0.0f, cB = 0.0f;
    float sA0 = 0, sA1 = 0, rA0 = 0, rA1 = 0;
    float sB0 = 0, sB1 = 0, rB0 = 0, rB1 = 0;

    // ---- x stagers: threads 0..55 -> (row sr, input sxi) ----
    const int  sr  = (tid >> 3) & 7;
    const int  sxi = tid & 7;
    const bool isStager = (tid < 56) && (sr < nrows);
    const float* xrow = x + (size_t)(rowbase + sr) * (TT * 8) + sxi;

    const uint32_t hB0 = (uint32_t)__cvta_generic_to_shared(&s_h[0][0][0]);
    const uint32_t hB1 = (uint32_t)__cvta_generic_to_shared(&s_h[1][0][0]);

    // ---- init BOTH buffers fully (phantom rows stay zero forever) ----
    for (int i = tid; i < 2 * RMAX * 72; i += 256)
        (&s_h[0][0][0])[i] = 0.0f;
    __syncthreads();
    if (isStager) s_h[0][sr][64 + sxi] = __ldg(xrow);
    __syncthreads();

    uint32_t rd = hB0, wr = hB1;

#pragma unroll 1
    for (int t = 0; t < TT; ++t) {
        float xn = 0.0f;
        const bool pre = isStager && (t + 1 < TT);
        if (pre) xn = __ldg(xrow + (t + 1) * 8);

        u64 p0, p1, q0, q1;

        // ---- rows 0-3, pipelined: RED(r) hides under DOT(r+1) ----
        DOT(0, p0, p1);
        DOT(1, q0, q1);
        RED(0, p0, p1);
        DOT(2, p0, p1);
        RED(1, q0, q1);
        DOT(3, q0, q1);
        RED(2, p0, p1);
        RED(3, q0, q1);

        // ---- updateA (rows 0-3 complete) — hidden under rows 4-6 FMA ----
        {
            float gi = gsel ? rA0 : sA0;
            float gf = gsel ? rA1 : sA1;
            float gg = gsel ? sA0 : rA0;
            float go = gsel ? sA1 : rA1;
            cA = fmaf(sigap(gf), cA, sigap(gi) * tanhap(gg));
            float hA = sigap(go) * tanhap(cA);
            asm volatile("st.shared.f32 [%0], %1;"
                         :: "r"(wr + rowA * 288 + u * 4), "f"(hA) : "memory");
            if (pre) {
                asm volatile("st.shared.f32 [%0], %1;"
                             :: "r"(wr + sr * 288 + (64 + sxi) * 4), "f"(xn) : "memory");
            }
        }

        // ---- rows 4-6, pipelined (row 6 may be phantom: zeros, self-contained) ----
        DOT(4, p0, p1);
        DOT(5, q0, q1);
        RED(4, p0, p1);
        DOT(6, p0, p1);
        RED(5, q0, q1);
        RED(6, p0, p1);

        // ---- updateB (lq<3; phantom row 6 update is harmless & bounded) ----
        if (hasB) {
            float gi = gsel ? rB0 : sB0;
            float gf = gsel ? rB1 : sB1;
            float gg = gsel ? sB0 : rB0;
            float go = gsel ? sB1 : rB1;
            cB = fmaf(sigap(gf), cB, sigap(gi) * tanhap(gg));
            float hBv = sigap(go) * tanhap(cB);
            asm volatile("st.shared.f32 [%0], %1;"
                         :: "r"(wr + rowB * 288 + u * 4), "f"(hBv) : "memory");
        }
        __syncthreads();

        uint32_t tmp = rd; rd = wr; wr = tmp;
    }

    // TT even -> final h lives in buf0
    if (tid < nrows) {
        const float* hp = s_h[0][tid];
        float acc = fcb[0];
#pragma unroll
        for (int uu = 0; uu < 64; ++uu)
            acc = fmaf(hp[uu], fcw[uu], acc);
        out[rowbase + tid] = sigap(acc);
    }
}

extern "C" void kernel_launch(void* const* d_in, const int* in_sizes, int n_in,
                              void* d_out, int out_size)
{
    const float* x   = (const float*)d_in[0];
    const float* Wih = (const float*)d_in[1];
    const float* Whh = (const float*)d_in[2];
    const float* bih = (const float*)d_in[3];
    const float* bhh = (const float*)d_in[4];
    const float* fcw = (const float*)d_in[5];
    const float* fcb = (const float*)d_in[6];
    lstm_kernel<<<296, 256>>>(x, Wih, Whh, bih, bhh, fcw, fcb, (float*)d_out);
}

// round 16
// speedup vs baseline: 2.5824x; 1.0618x over previous
#include <cuda_runtime.h>
#include <cstdint>

// LSTM: B=2048, T=1024, I=8, H=64. out = sigmoid(h_T @ fc_w^T + fc_b), [B,1] fp32.
//
// R15 = R9-1925 exactly (quad-gate: u=tid>>2, lane-in-quad = (K-half kh,
// gate-pair gsel); 2 outputs x 36 K in 36 packed f32x2 regs; per row 9 LDS.128
// + 36 FFMA2; split owner updates; ONE barrier/step; ping-pong h; grid 296)
// with the per-row gate-pair exchange (xor2) DEFERRED to update time:
// each lane stashes own-pair sums for its own row AND its partner lane's row;
// one xor2 shfl pair per update delivers partner gates. shfl/thread/step
// 28 -> 18; per-row tail loses one 26-cyc shfl chain stage.

#define TT   1024
#define RMAX 7

typedef unsigned long long u64;

__device__ __forceinline__ u64 pk2(float lo, float hi) {
    u64 r; asm("mov.b64 %0, {%1, %2};" : "=l"(r) : "f"(lo), "f"(hi)); return r;
}
__device__ __forceinline__ void upk2(u64 v, float& lo, float& hi) {
    asm("mov.b64 {%0, %1}, %2;" : "=f"(lo), "=f"(hi) : "l"(v));
}
__device__ __forceinline__ float tanhap(float x) {
    float r; asm("tanh.approx.f32 %0, %1;" : "=f"(r) : "f"(x)); return r;
}
__device__ __forceinline__ float sigap(float x) {
    return fmaf(0.5f, tanhap(0.5f * x), 0.5f);
}

// Row R: half-K dot on 2 outputs, fold, xor1-combine K-halves; stash own-pair
// sums if this lane owns row R (s*) or its partner lane owns row R (p*).
#define ROWG(R) do {                                                                \
    u64 _a0 = bias0, _a1 = bias1;                                                   \
    uint32_t _ad = rd + (R) * 288 + khoff;                                          \
    u64 _h01, _h23;                                                                 \
    _Pragma("unroll")                                                               \
    for (int q = 0; q < 9; ++q) {                                                   \
        asm("ld.shared.v2.u64 {%0, %1}, [%2];"                                      \
            : "=l"(_h01), "=l"(_h23) : "r"(_ad + q * 16));                          \
        asm("fma.rn.f32x2 %0, %1, %2, %0;" : "+l"(_a0) : "l"(w0[2*q]),   "l"(_h01));\
        asm("fma.rn.f32x2 %0, %1, %2, %0;" : "+l"(_a1) : "l"(w1[2*q]),   "l"(_h01));\
        asm("fma.rn.f32x2 %0, %1, %2, %0;" : "+l"(_a0) : "l"(w0[2*q+1]), "l"(_h23));\
        asm("fma.rn.f32x2 %0, %1, %2, %0;" : "+l"(_a1) : "l"(w1[2*q+1]), "l"(_h23));\
    }                                                                               \
    float _e0, _o0, _e1, _o1;                                                       \
    upk2(_a0, _e0, _o0); upk2(_a1, _e1, _o1);                                       \
    float _s0 = _e0 + _o0, _s1 = _e1 + _o1;                                         \
    _s0 += __shfl_xor_sync(0xffffffffu, _s0, 1);   /* combine K-halves */           \
    _s1 += __shfl_xor_sync(0xffffffffu, _s1, 1);                                    \
    if ((R) < 4) {                                                                  \
        if (lq  == (R)) { sA0 = _s0; sA1 = _s1; }                                   \
        if (lqx == (R)) { pA0 = _s0; pA1 = _s1; }                                   \
    } else {                                                                        \
        if (lq  == (R) - 4) { sB0 = _s0; sB1 = _s1; }                               \
        if (lqx == (R) - 4) { pB0 = _s0; pB1 = _s1; }                               \
    }                                                                               \
} while (0)

__global__ void __launch_bounds__(256, 2)
lstm_kernel(const float* __restrict__ x,     // [2048,1024,8]
            const float* __restrict__ Wih,   // [256,8]
            const float* __restrict__ Whh,   // [256,64]
            const float* __restrict__ bih,   // [256]
            const float* __restrict__ bhh,   // [256]
            const float* __restrict__ fcw,   // [64]
            const float* __restrict__ fcb,   // [1]
            float* __restrict__ out)         // [2048]
{
    __shared__ __align__(16) float s_h[2][RMAX][72];  // ping-pong: [buf][row][k]

    const int tid  = threadIdx.x;
    const int u    = tid >> 2;      // unit 0..63
    const int lq   = tid & 3;       // lane-in-quad
    const int lqx  = lq ^ 2;        // partner lane's quad index
    const int kh   = lq & 1;        // K-half
    const int gsel = lq >> 1;       // 0: owns (i,f); 1: owns (g,o)
    const int bid  = blockIdx.x;
    const int nrows   = (bid < 272) ? 7 : 6;
    const int rowbase = (bid < 272) ? bid * 7 : 1904 + (bid - 272) * 6;
    const bool seven  = (nrows == 7);

    const int jA = gsel * 128 + u;        // i (or g)
    const int jB = gsel * 128 + 64 + u;   // f (or o)
    const int kb = kh * 36;
    const uint32_t khoff = (uint32_t)(kb * 4);

    // ---- persistent weights: this K-half of outputs jA, jB ----
    u64 w0[18], w1[18];
#pragma unroll
    for (int q = 0; q < 18; ++q) {
        int k = kb + 2 * q;
        float a = (k     < 64) ? Whh[jA * 64 + k]     : Wih[jA * 8 + (k - 64)];
        float b = (k + 1 < 64) ? Whh[jA * 64 + k + 1] : Wih[jA * 8 + (k + 1 - 64)];
        float c = (k     < 64) ? Whh[jB * 64 + k]     : Wih[jB * 8 + (k - 64)];
        float d = (k + 1 < 64) ? Whh[jB * 64 + k + 1] : Wih[jB * 8 + (k + 1 - 64)];
        w0[q] = pk2(a, b);
        w1[q] = pk2(c, d);
    }
    u64 bias0 = 0ULL, bias1 = 0ULL;
    if (kh == 0) {   // bias counted exactly once per output
        bias0 = pk2(bih[jA] + bhh[jA], 0.0f);
        bias1 = pk2(bih[jB] + bhh[jB], 0.0f);
    }

    // ---- owned rows: rowA = lq, rowB = lq+4 (lq<3 and within nrows) ----
    const int rowA = lq, rowB = lq + 4;
    const bool hasB = (lq < 3) && (rowB < nrows);
    float cA = 0.0f, cB = 0.0f;
    float sA0 = 0, sA1 = 0, pA0 = 0, pA1 = 0;   // own-row / partner-row stashes
    float sB0 = 0, sB1 = 0, pB0 = 0, pB1 = 0;

    // ---- x stagers: threads 0..55 -> (row sr, input sxi) ----
    const int  sr  = (tid >> 3) & 7;
    const int  sxi = tid & 7;
    const bool isStager = (tid < 56) && (sr < nrows);
    const float* xrow = x + (size_t)(rowbase + sr) * (TT * 8) + sxi;

    const uint32_t hB0 = (uint32_t)__cvta_generic_to_shared(&s_h[0][0][0]);
    const uint32_t hB1 = (uint32_t)__cvta_generic_to_shared(&s_h[1][0][0]);

    // ---- init buf0: h = 0, x(0) staged ----
    for (int i = tid; i < RMAX * 72; i += 256)
        (&s_h[0][0][0])[i] = 0.0f;
    __syncthreads();
    if (isStager) s_h[0][sr][64 + sxi] = __ldg(xrow);
    __syncthreads();

    uint32_t rd = hB0, wr = hB1;

#pragma unroll 1
    for (int t = 0; t < TT; ++t) {
        float xn = 0.0f;
        const bool pre = isStager && (t + 1 < TT);
        if (pre) xn = __ldg(xrow + (t + 1) * 8);

        // ---- rows 0-3: dots + xor1 + stash ----
        ROWG(0); ROWG(1); ROWG(2); ROWG(3);

        // ---- updateA: one xor2 exchange, then activate (hidden under rows 4-6) ----
        {
            float recv0 = __shfl_xor_sync(0xffffffffu, pA0, 2);
            float recv1 = __shfl_xor_sync(0xffffffffu, pA1, 2);
            float gi = gsel ? recv0 : sA0;
            float gf = gsel ? recv1 : sA1;
            float gg = gsel ? sA0 : recv0;
            float go = gsel ? sA1 : recv1;
            cA = fmaf(sigap(gf), cA, sigap(gi) * tanhap(gg));
            float hA = sigap(go) * tanhap(cA);
            asm volatile("st.shared.f32 [%0], %1;"
                         :: "r"(wr + rowA * 288 + u * 4), "f"(hA) : "memory");
            if (pre) {
                asm volatile("st.shared.f32 [%0], %1;"
                             :: "r"(wr + sr * 288 + (64 + sxi) * 4), "f"(xn) : "memory");
            }
        }

        // ---- rows 4-6: dots + xor1 + stash ----
        ROWG(4); ROWG(5);
        if (seven) ROWG(6);

        // ---- updateB: shfl unguarded (full warp), update only if hasB ----
        {
            float recv0 = __shfl_xor_sync(0xffffffffu, pB0, 2);
            float recv1 = __shfl_xor_sync(0xffffffffu, pB1, 2);
            if (hasB) {
                float gi = gsel ? recv0 : sB0;
                float gf = gsel ? recv1 : sB1;
                float gg = gsel ? sB0 : recv0;
                float go = gsel ? sB1 : recv1;
                cB = fmaf(sigap(gf), cB, sigap(gi) * tanhap(gg));
                float hBv = sigap(go) * tanhap(cB);
                asm volatile("st.shared.f32 [%0], %1;"
                             :: "r"(wr + rowB * 288 + u * 4), "f"(hBv) : "memory");
            }
        }
        __syncthreads();

        uint32_t tmp = rd; rd = wr; wr = tmp;
    }

    // TT even -> final h lives in buf0
    if (tid < nrows) {
        const float* hp = s_h[0][tid];
        float acc = fcb[0];
#pragma unroll
        for (int uu = 0; uu < 64; ++uu)
            acc = fmaf(hp[uu], fcw[uu], acc);
        out[rowbase + tid] = sigap(acc);
    }
}

extern "C" void kernel_launch(void* const* d_in, const int* in_sizes, int n_in,
                              void* d_out, int out_size)
{
    const float* x   = (const float*)d_in[0];
    const float* Wih = (const float*)d_in[1];
    const float* Whh = (const float*)d_in[2];
    const float* bih = (const float*)d_in[3];
    const float* bhh = (const float*)d_in[4];
    const float* fcw = (const float*)d_in[5];
    const float* fcb = (const float*)d_in[6];
    lstm_kernel<<<296, 256>>>(x, Wih, Whh, bih, bhh, fcw, fcb, (float*)d_out);
}

// round 17
// speedup vs baseline: 2.6062x; 1.0092x over previous
#include <cuda_runtime.h>
#include <cstdint>

// LSTM: B=2048, T=1024, I=8, H=64. out = sigmoid(h_T @ fc_w^T + fc_b), [B,1] fp32.
//
// R16 = R15 (quad-gate, 2 outputs x 36 K in regs, 9 LDS.128 + 36 FFMA2 + xor1
// per row, deferred xor2 at update, ONE barrier/step, ping-pong h, grid 296)
// with warp-balanced x staging: warp w (w<7) lanes 0-7 stage row w's x values,
// so every warp carries the same load and the deterministic barrier straggler
// (old: all 56 stagers in warps 0-1) is gone. Buffer swap via XOR.

#define TT   1024
#define RMAX 7

typedef unsigned long long u64;

__device__ __forceinline__ u64 pk2(float lo, float hi) {
    u64 r; asm("mov.b64 %0, {%1, %2};" : "=l"(r) : "f"(lo), "f"(hi)); return r;
}
__device__ __forceinline__ void upk2(u64 v, float& lo, float& hi) {
    asm("mov.b64 {%0, %1}, %2;" : "=f"(lo), "=f"(hi) : "l"(v));
}
__device__ __forceinline__ float tanhap(float x) {
    float r; asm("tanh.approx.f32 %0, %1;" : "=f"(r) : "f"(x)); return r;
}
__device__ __forceinline__ float sigap(float x) {
    return fmaf(0.5f, tanhap(0.5f * x), 0.5f);
}

// Row R: half-K dot on 2 outputs, fold, xor1-combine K-halves; stash own-pair
// sums if this lane owns row R (s*) or its partner lane owns row R (p*).
#define ROWG(R) do {                                                                \
    u64 _a0 = bias0, _a1 = bias1;                                                   \
    uint32_t _ad = rd + (R) * 288 + khoff;                                          \
    u64 _h01, _h23;                                                                 \
    _Pragma("unroll")                                                               \
    for (int q = 0; q < 9; ++q) {                                                   \
        asm("ld.shared.v2.u64 {%0, %1}, [%2];"                                      \
            : "=l"(_h01), "=l"(_h23) : "r"(_ad + q * 16));                          \
        asm("fma.rn.f32x2 %0, %1, %2, %0;" : "+l"(_a0) : "l"(w0[2*q]),   "l"(_h01));\
        asm("fma.rn.f32x2 %0, %1, %2, %0;" : "+l"(_a1) : "l"(w1[2*q]),   "l"(_h01));\
        asm("fma.rn.f32x2 %0, %1, %2, %0;" : "+l"(_a0) : "l"(w0[2*q+1]), "l"(_h23));\
        asm("fma.rn.f32x2 %0, %1, %2, %0;" : "+l"(_a1) : "l"(w1[2*q+1]), "l"(_h23));\
    }                                                                               \
    float _e0, _o0, _e1, _o1;                                                       \
    upk2(_a0, _e0, _o0); upk2(_a1, _e1, _o1);                                       \
    float _s0 = _e0 + _o0, _s1 = _e1 + _o1;                                         \
    _s0 += __shfl_xor_sync(0xffffffffu, _s0, 1);   /* combine K-halves */           \
    _s1 += __shfl_xor_sync(0xffffffffu, _s1, 1);                                    \
    if ((R) < 4) {                                                                  \
        if (lq  == (R)) { sA0 = _s0; sA1 = _s1; }                                   \
        if (lqx == (R)) { pA0 = _s0; pA1 = _s1; }                                   \
    } else {                                                                        \
        if (lq  == (R) - 4) { sB0 = _s0; sB1 = _s1; }                               \
        if (lqx == (R) - 4) { pB0 = _s0; pB1 = _s1; }                               \
    }                                                                               \
} while (0)

__global__ void __launch_bounds__(256, 2)
lstm_kernel(const float* __restrict__ x,     // [2048,1024,8]
            const float* __restrict__ Wih,   // [256,8]
            const float* __restrict__ Whh,   // [256,64]
            const float* __restrict__ bih,   // [256]
            const float* __restrict__ bhh,   // [256]
            const float* __restrict__ fcw,   // [64]
            const float* __restrict__ fcb,   // [1]
            float* __restrict__ out)         // [2048]
{
    __shared__ __align__(16) float s_h[2][RMAX][72];  // ping-pong: [buf][row][k]

    const int tid  = threadIdx.x;
    const int lane = tid & 31;
    const int wid  = tid >> 5;
    const int u    = tid >> 2;      // unit 0..63
    const int lq   = tid & 3;       // lane-in-quad
    const int lqx  = lq ^ 2;        // partner lane's quad index
    const int kh   = lq & 1;        // K-half
    const int gsel = lq >> 1;       // 0: owns (i,f); 1: owns (g,o)
    const int bid  = blockIdx.x;
    const int nrows   = (bid < 272) ? 7 : 6;
    const int rowbase = (bid < 272) ? bid * 7 : 1904 + (bid - 272) * 6;
    const bool seven  = (nrows == 7);

    const int jA = gsel * 128 + u;        // i (or g)
    const int jB = gsel * 128 + 64 + u;   // f (or o)
    const int kb = kh * 36;
    const uint32_t khoff = (uint32_t)(kb * 4);

    // ---- persistent weights: this K-half of outputs jA, jB ----
    u64 w0[18], w1[18];
#pragma unroll
    for (int q = 0; q < 18; ++q) {
        int k = kb + 2 * q;
        float a = (k     < 64) ? Whh[jA * 64 + k]     : Wih[jA * 8 + (k - 64)];
        float b = (k + 1 < 64) ? Whh[jA * 64 + k + 1] : Wih[jA * 8 + (k + 1 - 64)];
        float c = (k     < 64) ? Whh[jB * 64 + k]     : Wih[jB * 8 + (k - 64)];
        float d = (k + 1 < 64) ? Whh[jB * 64 + k + 1] : Wih[jB * 8 + (k + 1 - 64)];
        w0[q] = pk2(a, b);
        w1[q] = pk2(c, d);
    }
    u64 bias0 = 0ULL, bias1 = 0ULL;
    if (kh == 0) {   // bias counted exactly once per output
        bias0 = pk2(bih[jA] + bhh[jA], 0.0f);
        bias1 = pk2(bih[jB] + bhh[jB], 0.0f);
    }

    // ---- owned rows: rowA = lq, rowB = lq+4 (lq<3 and within nrows) ----
    const int rowA = lq, rowB = lq + 4;
    const bool hasB = (lq < 3) && (rowB < nrows);
    float cA = 0.0f, cB = 0.0f;
    float sA0 = 0, sA1 = 0, pA0 = 0, pA1 = 0;   // own-row / partner-row stashes
    float sB0 = 0, sB1 = 0, pB0 = 0, pB1 = 0;

    // ---- x stagers, warp-balanced: warp w (w < nrows), lanes 0-7 stage row w ----
    const int  sr  = wid;                 // staged row = warp id
    const int  sxi = lane;                // staged input = lane (0..7)
    const bool isStager = (lane < 8) && (wid < nrows);
    const float* xrow = x + (size_t)(rowbase + (sr < RMAX ? sr : 0)) * (TT * 8) + sxi;

    const uint32_t hB0 = (uint32_t)__cvta_generic_to_shared(&s_h[0][0][0]);
    const uint32_t hB1 = (uint32_t)__cvta_generic_to_shared(&s_h[1][0][0]);
    const uint32_t hXOR = hB0 ^ hB1;

    // ---- init buf0: h = 0, x(0) staged ----
    for (int i = tid; i < RMAX * 72; i += 256)
        (&s_h[0][0][0])[i] = 0.0f;
    __syncthreads();
    if (isStager) s_h[0][sr][64 + sxi] = __ldg(xrow);
    __syncthreads();

    uint32_t rd = hB0;

#pragma unroll 1
    for (int t = 0; t < TT; ++t) {
        const uint32_t wr = rd ^ hXOR;
        float xn = 0.0f;
        const bool pre = isStager && (t + 1 < TT);
        if (pre) xn = __ldg(xrow + (t + 1) * 8);

        // ---- rows 0-3: dots + xor1 + stash ----
        ROWG(0); ROWG(1); ROWG(2); ROWG(3);

        // ---- updateA: one xor2 exchange, then activate (hidden under rows 4-6) ----
        {
            float recv0 = __shfl_xor_sync(0xffffffffu, pA0, 2);
            float recv1 = __shfl_xor_sync(0xffffffffu, pA1, 2);
            float gi = gsel ? recv0 : sA0;
            float gf = gsel ? recv1 : sA1;
            float gg = gsel ? sA0 : recv0;
            float go = gsel ? sA1 : recv1;
            cA = fmaf(sigap(gf), cA, sigap(gi) * tanhap(gg));
            float hA = sigap(go) * tanhap(cA);
            asm volatile("st.shared.f32 [%0], %1;"
                         :: "r"(wr + rowA * 288 + u * 4), "f"(hA) : "memory");
            if (pre) {
                asm volatile("st.shared.f32 [%0], %1;"
                             :: "r"(wr + sr * 288 + (64 + sxi) * 4), "f"(xn) : "memory");
            }
        }

        // ---- rows 4-6: dots + xor1 + stash ----
        ROWG(4); ROWG(5);
        if (seven) ROWG(6);

        // ---- updateB: shfl unguarded (full warp), update only if hasB ----
        {
            float recv0 = __shfl_xor_sync(0xffffffffu, pB0, 2);
            float recv1 = __shfl_xor_sync(0xffffffffu, pB1, 2);
            if (hasB) {
                float gi = gsel ? recv0 : sB0;
                float gf = gsel ? recv1 : sB1;
                float gg = gsel ? sB0 : recv0;
                float go = gsel ? sB1 : recv1;
                cB = fmaf(sigap(gf), cB, sigap(gi) * tanhap(gg));
                float hBv = sigap(go) * tanhap(cB);
                asm volatile("st.shared.f32 [%0], %1;"
                             :: "r"(wr + rowB * 288 + u * 4), "f"(hBv) : "memory");
            }
        }
        __syncthreads();

        rd = wr;
    }

    // TT even -> final h lives in buf0
    if (tid < nrows) {
        const float* hp = s_h[0][tid];
        float acc = fcb[0];
#pragma unroll
        for (int uu = 0; uu < 64; ++uu)
            acc = fmaf(hp[uu], fcw[uu], acc);
        out[rowbase + tid] = sigap(acc);
    }
}

extern "C" void kernel_launch(void* const* d_in, const int* in_sizes, int n_in,
                              void* d_out, int out_size)
{
    const float* x   = (const float*)d_in[0];
    const float* Wih = (const float*)d_in[1];
    const float* Whh = (const float*)d_in[2];
    const float* bih = (const float*)d_in[3];
    const float* bhh = (const float*)d_in[4];
    const float* fcw = (const float*)d_in[5];
    const float* fcb = (const float*)d_in[6];
    lstm_kernel<<<296, 256>>>(x, Wih, Whh, bih, bhh, fcw, fcb, (float*)d_out);
}